// round 15
// baseline (speedup 1.0000x reference)
#include <cuda_runtime.h>
#include <cuda_fp16.h>
#include <cstdint>

// ============================================================================
// out[b,n,m] = <x[b,n,:], y[b,m,:]> / max(||x[b,n]|| * ||y[b,m]||, eps)
//   x, y: [8, 2048, 512] fp32 ; out: [8, 2048, 2048] fp32
//
// Round 15: single-pass fp16, smem-byte reduction:
//   - warp tile 64x64 (acc 128 regs), CTA 128x128, 4 warps 2x2
//   - LDSM+STS falls 4.5 -> 3.0 B/output-elem: L1 floor ~47us < tensor 52-57us
//   - 4-stage single-barrier ring, interleaved cp.async, reciprocal epilogue,
//     streaming stores. ~190 regs -> 2 CTAs/SM.
// ============================================================================

#define Bq 8
#define Nq 2048
#define Dq 512
#define EPSq 1e-8f

#define BMq 128
#define BNq 128
#define BKq 32                 // 32 fp16 = 64B per row
#define KITER (Dq / BKq)       // 16

// per-stage: A 8K | B 8K = 16KB; 4 stages = 64KB
#define A_OFF      0
#define B_OFF      8192
#define STG_BYTES  16384
#define SMEM_TOTAL (4 * STG_BYTES)   // 65536

#define ROW32 (32 * Dq)

__device__ float g_xin[Bq * Nq];   // 1 / ||x_row||
__device__ float g_yin[Bq * Nq];   // 1 / ||y_row||
__device__ __half g_xh[Bq * Nq * Dq];
__device__ __half g_yh[Bq * Nq * Dq];

// ---------------------------------------------------------------------------
__device__ __forceinline__ uint32_t smem_u32(const void* p) {
    uint32_t a;
    asm("{ .reg .u64 t; cvta.to.shared.u64 t, %1; cvt.u32.u64 %0, t; }"
        : "=r"(a) : "l"(p));
    return a;
}

#define CP_ASYNC16(dst, src) \
    asm volatile("cp.async.cg.shared.global [%0], [%1], 16;" \
                 :: "r"(dst), "l"(src) : "memory")
#define CP_COMMIT() asm volatile("cp.async.commit_group;" ::: "memory")
#define CP_WAIT2()  asm volatile("cp.async.wait_group 2;" ::: "memory")

#define LDSM4(r, addr) \
    asm volatile("ldmatrix.sync.aligned.m8n8.x4.shared.b16 {%0,%1,%2,%3}, [%4];" \
                 : "=r"((r)[0]), "=r"((r)[1]), "=r"((r)[2]), "=r"((r)[3]) \
                 : "r"(addr))

#define MMA_F16(d, a, bf) \
    asm volatile("mma.sync.aligned.m16n8k16.row.col.f32.f16.f16.f32 " \
                 "{%0,%1,%2,%3}, {%4,%5,%6,%7}, {%8,%9}, {%0,%1,%2,%3};" \
                 : "+f"((d)[0]), "+f"((d)[1]), "+f"((d)[2]), "+f"((d)[3]) \
                 : "r"((a)[0]), "r"((a)[1]), "r"((a)[2]), "r"((a)[3]), \
                   "r"((bf)[0]), "r"((bf)[1]))

#define STG_CS_V2(addr, vx, vy) \
    asm volatile("st.global.cs.v2.f32 [%0], {%1, %2};" \
                 :: "l"(addr), "f"(vx), "f"(vy) : "memory")

// paired-row swizzle for 64B rows
__device__ __forceinline__ uint32_t swz64(int r, int c) {
    uint32_t line = (uint32_t)r >> 1;
    uint32_t ce = (((uint32_t)r & 1u) << 2) | (uint32_t)c;
    return line * 128u + ((ce ^ (line & 7u)) << 4);
}

// ---------------------------------------------------------------------------
// Prep: one warp per row: inverse norms (fp32 exact) + fp16 conversion.
// ---------------------------------------------------------------------------
__global__ void __launch_bounds__(256) prep_kernel(const float* __restrict__ X,
                                                   const float* __restrict__ Y) {
    int row = blockIdx.x * 8 + (threadIdx.x >> 5);
    int lane = threadIdx.x & 31;
    if (row >= Bq * Nq) return;

    const float4* px = reinterpret_cast<const float4*>(X + (size_t)row * Dq);
    const float4* py = reinterpret_cast<const float4*>(Y + (size_t)row * Dq);

    float sx = 0.f, sy = 0.f;
#pragma unroll
    for (int v = 0; v < 4; v++) {
        int i = v * 32 + lane;
        size_t off = (size_t)row * Dq + (size_t)i * 4;
        {
            float4 a = px[i];
            sx = fmaf(a.x, a.x, sx); sx = fmaf(a.y, a.y, sx);
            sx = fmaf(a.z, a.z, sx); sx = fmaf(a.w, a.w, sx);
            __half2 h0 = __float22half2_rn(make_float2(a.x, a.y));
            __half2 h1 = __float22half2_rn(make_float2(a.z, a.w));
            *reinterpret_cast<__half2*>(g_xh + off)     = h0;
            *reinterpret_cast<__half2*>(g_xh + off + 2) = h1;
        }
        {
            float4 a = py[i];
            sy = fmaf(a.x, a.x, sy); sy = fmaf(a.y, a.y, sy);
            sy = fmaf(a.z, a.z, sy); sy = fmaf(a.w, a.w, sy);
            __half2 h0 = __float22half2_rn(make_float2(a.x, a.y));
            __half2 h1 = __float22half2_rn(make_float2(a.z, a.w));
            *reinterpret_cast<__half2*>(g_yh + off)     = h0;
            *reinterpret_cast<__half2*>(g_yh + off + 2) = h1;
        }
    }
#pragma unroll
    for (int off = 16; off > 0; off >>= 1) {
        sx += __shfl_xor_sync(0xFFFFFFFFu, sx, off);
        sy += __shfl_xor_sync(0xFFFFFFFFu, sy, off);
    }
    if (lane == 0) {
        g_xin[row] = 1.0f / fmaxf(sqrtf(sx), 1e-30f);
        g_yin[row] = 1.0f / fmaxf(sqrtf(sy), 1e-30f);
    }
}

// ---------------------------------------------------------------------------
// GEMM kernel. Grid (16,16,8) = 2048 CTAs, 128 threads = 4 warps (2x2),
// warp tile 64x64. ~2 CTAs/SM (reg-limited). 4-stage single-barrier ring.
// ---------------------------------------------------------------------------
__global__ void __launch_bounds__(128) cosine_mma_kernel(float* __restrict__ out) {
    extern __shared__ char smem[];
    const uint32_t sb = smem_u32(smem);

    const int tid = threadIdx.x;
    const int wid = tid >> 5, lane = tid & 31;
    const int wm = wid >> 1;          // 0..1  (64 m-rows)
    const int wn = wid & 1;           // 0..1  (64 n-cols)
    const int tileM = blockIdx.x;     // y tile (128 rows)
    const int tileN = blockIdx.y;     // x tile (128 rows)
    const int b = blockIdx.z;
    const int rowA0 = tileN * BMq;
    const int rowB0 = tileM * BNq;

    // ---- cp.async setup: A 128 rows x 4 chunks + B 128 rows x 4 chunks ----
    const int r0 = tid >> 2;          // 0..31
    const int c0 = tid & 3;
    const uint32_t d0 = swz64(r0, c0);
    const __half* pxh = g_xh + (size_t)(b * Nq + rowA0 + r0) * Dq + c0 * 8;
    const __half* pyh = g_yh + (size_t)(b * Nq + rowB0 + r0) * Dq + c0 * 8;

#define LOAD_STAGE_ALL(ST) do {                                      \
        CP_ASYNC16((ST) + A_OFF + d0,        pxh);                   \
        CP_ASYNC16((ST) + A_OFF + d0 + 2048, pxh + ROW32);           \
        CP_ASYNC16((ST) + A_OFF + d0 + 4096, pxh + 2 * ROW32);       \
        CP_ASYNC16((ST) + A_OFF + d0 + 6144, pxh + 3 * ROW32);       \
        CP_ASYNC16((ST) + B_OFF + d0,        pyh);                   \
        CP_ASYNC16((ST) + B_OFF + d0 + 2048, pyh + ROW32);           \
        CP_ASYNC16((ST) + B_OFF + d0 + 4096, pyh + 2 * ROW32);       \
        CP_ASYNC16((ST) + B_OFF + d0 + 6144, pyh + 3 * ROW32);       \
        pxh += BKq; pyh += BKq;                                      \
    } while (0)

    float acc[4][8][4];
#pragma unroll
    for (int i = 0; i < 4; i++)
#pragma unroll
        for (int j = 0; j < 8; j++)
#pragma unroll
            for (int r = 0; r < 4; r++) acc[i][j][r] = 0.f;

    // prologue: 3 stages in flight (k-tiles 0,1,2)
    LOAD_STAGE_ALL(sb + 0 * STG_BYTES); CP_COMMIT();
    LOAD_STAGE_ALL(sb + 1 * STG_BYTES); CP_COMMIT();
    LOAD_STAGE_ALL(sb + 2 * STG_BYTES); CP_COMMIT();

    // ---- fully precomputed fragment smem offsets ----
    const int rowSel = (lane & 7) + (((lane >> 3) & 1) << 3);  // 0..15
    const uint32_t kcq = (uint32_t)(lane >> 4);                // 0/1

    uint32_t aOff[4][2], bOff[4][2];
#pragma unroll
    for (int mi = 0; mi < 4; mi++) {
        int row = wm * 64 + mi * 16 + rowSel;
        uint32_t line = (uint32_t)(row >> 1);
        uint32_t par  = ((uint32_t)row & 1u) << 2;
#pragma unroll
        for (int k16 = 0; k16 < 2; k16++) {
            uint32_t kc = (uint32_t)(k16 * 2) + kcq;
            aOff[mi][k16] = A_OFF + line * 128u + (((par | kc) ^ (line & 7u)) << 4);
        }
    }
#pragma unroll
    for (int nj = 0; nj < 4; nj++) {
        int row = wn * 64 + nj * 16 + rowSel;
        uint32_t line = (uint32_t)(row >> 1);
        uint32_t par  = ((uint32_t)row & 1u) << 2;
#pragma unroll
        for (int k16 = 0; k16 < 2; k16++) {
            uint32_t kc = (uint32_t)(k16 * 2) + kcq;
            bOff[nj][k16] = B_OFF + line * 128u + (((par | kc) ^ (line & 7u)) << 4);
        }
    }

    for (int t = 0; t < KITER; t++) {
        CP_WAIT2();                      // stage t&3 ready
        __syncthreads();                 // everyone finished iter t-1 reads

        const uint32_t st = sb + (t & 3) * STG_BYTES;
        const bool doLoad = (t + 3 < KITER);
        const uint32_t ld = sb + ((t + 3) & 3) * STG_BYTES;  // == (t-1)&3, safe

#pragma unroll
        for (int k16 = 0; k16 < 2; k16++) {
            // ---- B fragments for this k16: 8 n-blocks ----
            uint32_t bf[8][2];
#pragma unroll
            for (int nj = 0; nj < 4; nj++) {
                uint32_t tb[4];
                LDSM4(tb, st + bOff[nj][k16]);
                bf[2 * nj][0] = tb[0]; bf[2 * nj][1] = tb[2];
                bf[2 * nj + 1][0] = tb[1]; bf[2 * nj + 1][1] = tb[3];
            }
            // interleaved global loads (4 per k16)
            if (doLoad) {
                if (k16 == 0) {
                    CP_ASYNC16(ld + A_OFF + d0,        pxh);
                    CP_ASYNC16(ld + A_OFF + d0 + 2048, pxh + ROW32);
                } else {
                    CP_ASYNC16(ld + B_OFF + d0,        pyh);
                    CP_ASYNC16(ld + B_OFF + d0 + 2048, pyh + ROW32);
                }
            }

            // ---- A per mi, double-buffered; 8-MMA runs ----
            uint32_t af[2][4];
            LDSM4(af[0], st + aOff[0][k16]);
#pragma unroll
            for (int mi = 0; mi < 4; mi++) {
                const int cur = mi & 1, nxt = cur ^ 1;
                if (mi < 3) {
                    LDSM4(af[nxt], st + aOff[mi + 1][k16]);
                }
#pragma unroll
                for (int ni = 0; ni < 8; ni++)
                    MMA_F16(acc[mi][ni], af[cur], bf[ni]);

                if (doLoad && mi == 1) {
                    if (k16 == 0) {
                        CP_ASYNC16(ld + A_OFF + d0 + 4096, pxh + 2 * ROW32);
                        CP_ASYNC16(ld + A_OFF + d0 + 6144, pxh + 3 * ROW32);
                    } else {
                        CP_ASYNC16(ld + B_OFF + d0 + 4096, pyh + 2 * ROW32);
                        CP_ASYNC16(ld + B_OFF + d0 + 6144, pyh + 3 * ROW32);
                    }
                }
            }
        }
        if (doLoad) { pxh += BKq; pyh += BKq; }
        CP_COMMIT();                     // exactly one group per iter
    }

    // ---- fused cosine epilogue (reciprocal multiplies, streaming stores) ----
    const int gq = lane >> 2;
    const int tq = lane & 3;

    float yi0[8], yi1[8];
#pragma unroll
    for (int ni = 0; ni < 8; ni++) {
        int n = rowB0 + wn * 64 + ni * 8 + 2 * tq;
        yi0[ni] = g_yin[b * Nq + n];
        yi1[ni] = g_yin[b * Nq + n + 1];
    }

#pragma unroll
    for (int mi = 0; mi < 4; mi++) {
        int mA = rowA0 + wm * 64 + mi * 16 + gq;
        float xiA = g_xin[b * Nq + mA];
        float xiB = g_xin[b * Nq + mA + 8];
        float* orowA = out + ((size_t)b * Nq + mA) * Nq + rowB0 + wn * 64;
        float* orowB = orowA + 8 * (size_t)Nq;
#pragma unroll
        for (int ni = 0; ni < 8; ni++) {
            STG_CS_V2(orowA + ni * 8 + 2 * tq,
                      acc[mi][ni][0] * (xiA * yi0[ni]),
                      acc[mi][ni][1] * (xiA * yi1[ni]));
            STG_CS_V2(orowB + ni * 8 + 2 * tq,
                      acc[mi][ni][2] * (xiB * yi0[ni]),
                      acc[mi][ni][3] * (xiB * yi1[ni]));
        }
    }
}

// ---------------------------------------------------------------------------
extern "C" void kernel_launch(void* const* d_in, const int* in_sizes, int n_in,
                              void* d_out, int out_size) {
    const float* x = (const float*)d_in[0];
    const float* y = (const float*)d_in[1];
    float* out = (float*)d_out;

    prep_kernel<<<(Bq * Nq + 7) / 8, 256>>>(x, y);

    cudaFuncSetAttribute(cosine_mma_kernel,
                         cudaFuncAttributeMaxDynamicSharedMemorySize, SMEM_TOTAL);
    dim3 grid(Nq / BNq, Nq / BMq, Bq);   // (16, 16, 8)
    cosine_mma_kernel<<<grid, 128, SMEM_TOTAL>>>(out);
}

// round 16
// speedup vs baseline: 1.0427x; 1.0427x over previous
#include <cuda_runtime.h>
#include <cuda_fp16.h>
#include <cstdint>

// ============================================================================
// out[b,n,m] = <x[b,n,:], y[b,m,:]> / max(||x[b,n]|| * ||y[b,m]||, eps)
//   x, y: [8, 2048, 512] fp32 ; out: [8, 2048, 2048] fp32
//
// Round 16: single-pass fp16. R14 machinery, CTA 128x128 / 8 warps (2x4),
//   warp tile 64x32 (R14's proven shape): -11% smem bytes/output at the SAME
//   16 warps/SM (128 regs, 64KB smem -> 2 CTAs/SM). Half the CTAs, half the
//   B global re-reads. 4-stage single-barrier ring, interleaved cp.async,
//   reciprocal epilogue, streaming stores.
// ============================================================================

#define Bq 8
#define Nq 2048
#define Dq 512
#define EPSq 1e-8f

#define BMq 128
#define BNq 128
#define BKq 32                 // 32 fp16 = 64B per row
#define KITER (Dq / BKq)       // 16

// per-stage: A 8K | B 8K = 16KB; 4 stages = 64KB
#define A_OFF      0
#define B_OFF      8192
#define STG_BYTES  16384
#define SMEM_TOTAL (4 * STG_BYTES)   // 65536

#define ROW64 (64 * Dq)

__device__ float g_xin[Bq * Nq];   // 1 / ||x_row||
__device__ float g_yin[Bq * Nq];   // 1 / ||y_row||
__device__ __half g_xh[Bq * Nq * Dq];
__device__ __half g_yh[Bq * Nq * Dq];

// ---------------------------------------------------------------------------
__device__ __forceinline__ uint32_t smem_u32(const void* p) {
    uint32_t a;
    asm("{ .reg .u64 t; cvta.to.shared.u64 t, %1; cvt.u32.u64 %0, t; }"
        : "=r"(a) : "l"(p));
    return a;
}

#define CP_ASYNC16(dst, src) \
    asm volatile("cp.async.cg.shared.global [%0], [%1], 16;" \
                 :: "r"(dst), "l"(src) : "memory")
#define CP_COMMIT() asm volatile("cp.async.commit_group;" ::: "memory")
#define CP_WAIT2()  asm volatile("cp.async.wait_group 2;" ::: "memory")

#define LDSM4(r, addr) \
    asm volatile("ldmatrix.sync.aligned.m8n8.x4.shared.b16 {%0,%1,%2,%3}, [%4];" \
                 : "=r"((r)[0]), "=r"((r)[1]), "=r"((r)[2]), "=r"((r)[3]) \
                 : "r"(addr))

#define MMA_F16(d, a, bf) \
    asm volatile("mma.sync.aligned.m16n8k16.row.col.f32.f16.f16.f32 " \
                 "{%0,%1,%2,%3}, {%4,%5,%6,%7}, {%8,%9}, {%0,%1,%2,%3};" \
                 : "+f"((d)[0]), "+f"((d)[1]), "+f"((d)[2]), "+f"((d)[3]) \
                 : "r"((a)[0]), "r"((a)[1]), "r"((a)[2]), "r"((a)[3]), \
                   "r"((bf)[0]), "r"((bf)[1]))

#define STG_CS_V2(addr, vx, vy) \
    asm volatile("st.global.cs.v2.f32 [%0], {%1, %2};" \
                 :: "l"(addr), "f"(vx), "f"(vy) : "memory")

// paired-row swizzle for 64B rows
__device__ __forceinline__ uint32_t swz64(int r, int c) {
    uint32_t line = (uint32_t)r >> 1;
    uint32_t ce = (((uint32_t)r & 1u) << 2) | (uint32_t)c;
    return line * 128u + ((ce ^ (line & 7u)) << 4);
}

// ---------------------------------------------------------------------------
// Prep: one warp per row: inverse norms (fp32 exact) + fp16 conversion.
// ---------------------------------------------------------------------------
__global__ void __launch_bounds__(256) prep_kernel(const float* __restrict__ X,
                                                   const float* __restrict__ Y) {
    int row = blockIdx.x * 8 + (threadIdx.x >> 5);
    int lane = threadIdx.x & 31;
    if (row >= Bq * Nq) return;

    const float4* px = reinterpret_cast<const float4*>(X + (size_t)row * Dq);
    const float4* py = reinterpret_cast<const float4*>(Y + (size_t)row * Dq);

    float sx = 0.f, sy = 0.f;
#pragma unroll
    for (int v = 0; v < 4; v++) {
        int i = v * 32 + lane;
        size_t off = (size_t)row * Dq + (size_t)i * 4;
        {
            float4 a = px[i];
            sx = fmaf(a.x, a.x, sx); sx = fmaf(a.y, a.y, sx);
            sx = fmaf(a.z, a.z, sx); sx = fmaf(a.w, a.w, sx);
            __half2 h0 = __float22half2_rn(make_float2(a.x, a.y));
            __half2 h1 = __float22half2_rn(make_float2(a.z, a.w));
            *reinterpret_cast<__half2*>(g_xh + off)     = h0;
            *reinterpret_cast<__half2*>(g_xh + off + 2) = h1;
        }
        {
            float4 a = py[i];
            sy = fmaf(a.x, a.x, sy); sy = fmaf(a.y, a.y, sy);
            sy = fmaf(a.z, a.z, sy); sy = fmaf(a.w, a.w, sy);
            __half2 h0 = __float22half2_rn(make_float2(a.x, a.y));
            __half2 h1 = __float22half2_rn(make_float2(a.z, a.w));
            *reinterpret_cast<__half2*>(g_yh + off)     = h0;
            *reinterpret_cast<__half2*>(g_yh + off + 2) = h1;
        }
    }
#pragma unroll
    for (int off = 16; off > 0; off >>= 1) {
        sx += __shfl_xor_sync(0xFFFFFFFFu, sx, off);
        sy += __shfl_xor_sync(0xFFFFFFFFu, sy, off);
    }
    if (lane == 0) {
        g_xin[row] = 1.0f / fmaxf(sqrtf(sx), 1e-30f);
        g_yin[row] = 1.0f / fmaxf(sqrtf(sy), 1e-30f);
    }
}

// ---------------------------------------------------------------------------
// GEMM kernel. Grid (16,16,8) = 2048 CTAs, 256 threads = 8 warps (2x4),
// warp tile 64x32. 2 CTAs/SM (16 warps). 4-stage single-barrier ring.
// ---------------------------------------------------------------------------
__global__ void __launch_bounds__(256, 2) cosine_mma_kernel(float* __restrict__ out) {
    extern __shared__ char smem[];
    const uint32_t sb = smem_u32(smem);

    const int tid = threadIdx.x;
    const int wid = tid >> 5, lane = tid & 31;
    const int wm = wid >> 2;          // 0..1  (64 m-rows)
    const int wn = wid & 3;           // 0..3  (32 n-cols)
    const int tileM = blockIdx.x;     // y tile (128 rows)
    const int tileN = blockIdx.y;     // x tile (128 rows)
    const int b = blockIdx.z;
    const int rowA0 = tileN * BMq;
    const int rowB0 = tileM * BNq;

    // ---- cp.async setup: A/B 128 rows x 4 chunks each; 4 cp per thread ----
    const int r0 = tid >> 2;          // 0..63
    const int c0 = tid & 3;
    const uint32_t d0 = swz64(r0, c0);       // rows r0+64: offset d0 + 4096
    const __half* pxh = g_xh + (size_t)(b * Nq + rowA0 + r0) * Dq + c0 * 8;
    const __half* pyh = g_yh + (size_t)(b * Nq + rowB0 + r0) * Dq + c0 * 8;

#define LOAD_STAGE_ALL(ST) do {                                      \
        CP_ASYNC16((ST) + A_OFF + d0,        pxh);                   \
        CP_ASYNC16((ST) + A_OFF + d0 + 4096, pxh + ROW64);           \
        CP_ASYNC16((ST) + B_OFF + d0,        pyh);                   \
        CP_ASYNC16((ST) + B_OFF + d0 + 4096, pyh + ROW64);           \
        pxh += BKq; pyh += BKq;                                      \
    } while (0)

    float acc[4][4][4];
#pragma unroll
    for (int i = 0; i < 4; i++)
#pragma unroll
        for (int j = 0; j < 4; j++)
#pragma unroll
            for (int r = 0; r < 4; r++) acc[i][j][r] = 0.f;

    // prologue: 3 stages in flight (k-tiles 0,1,2)
    LOAD_STAGE_ALL(sb + 0 * STG_BYTES); CP_COMMIT();
    LOAD_STAGE_ALL(sb + 1 * STG_BYTES); CP_COMMIT();
    LOAD_STAGE_ALL(sb + 2 * STG_BYTES); CP_COMMIT();

    // ---- fully precomputed fragment smem offsets ----
    const int rowSel = (lane & 7) + (((lane >> 3) & 1) << 3);  // 0..15
    const uint32_t kcq = (uint32_t)(lane >> 4);                // 0/1

    uint32_t aOff[4][2], bOff[2][2];
#pragma unroll
    for (int mi = 0; mi < 4; mi++) {
        int row = wm * 64 + mi * 16 + rowSel;
        uint32_t line = (uint32_t)(row >> 1);
        uint32_t par  = ((uint32_t)row & 1u) << 2;
#pragma unroll
        for (int k16 = 0; k16 < 2; k16++) {
            uint32_t kc = (uint32_t)(k16 * 2) + kcq;
            aOff[mi][k16] = A_OFF + line * 128u + (((par | kc) ^ (line & 7u)) << 4);
        }
    }
#pragma unroll
    for (int nj = 0; nj < 2; nj++) {
        int row = wn * 32 + nj * 16 + rowSel;
        uint32_t line = (uint32_t)(row >> 1);
        uint32_t par  = ((uint32_t)row & 1u) << 2;
#pragma unroll
        for (int k16 = 0; k16 < 2; k16++) {
            uint32_t kc = (uint32_t)(k16 * 2) + kcq;
            bOff[nj][k16] = B_OFF + line * 128u + (((par | kc) ^ (line & 7u)) << 4);
        }
    }

    for (int t = 0; t < KITER; t++) {
        CP_WAIT2();                      // stage t&3 ready
        __syncthreads();                 // everyone finished iter t-1 reads

        const uint32_t st = sb + (t & 3) * STG_BYTES;
        const bool doLoad = (t + 3 < KITER);
        const uint32_t ld = sb + ((t + 3) & 3) * STG_BYTES;  // == (t-1)&3, safe

        // ---- B fragments for BOTH k16 halves ----
        uint32_t bf[2][4][2];
#pragma unroll
        for (int k16 = 0; k16 < 2; k16++) {
#pragma unroll
            for (int nj = 0; nj < 2; nj++) {
                uint32_t tb[4];
                LDSM4(tb, st + bOff[nj][k16]);
                bf[k16][2 * nj][0] = tb[0]; bf[k16][2 * nj][1] = tb[2];
                bf[k16][2 * nj + 1][0] = tb[1]; bf[k16][2 * nj + 1][1] = tb[3];
            }
        }
        // interleaved loads, chunk 1/3
        if (doLoad) {
            CP_ASYNC16(ld + A_OFF + d0,        pxh);
            CP_ASYNC16(ld + A_OFF + d0 + 4096, pxh + ROW64);
        }

        // ---- A per mi (both k16), double-buffered; 8-MMA runs ----
        uint32_t af[2][2][4];
        LDSM4(af[0][0], st + aOff[0][0]);
        LDSM4(af[0][1], st + aOff[0][1]);
#pragma unroll
        for (int mi = 0; mi < 4; mi++) {
            const int cur = mi & 1, nxt = cur ^ 1;
            if (mi < 3) {
                LDSM4(af[nxt][0], st + aOff[mi + 1][0]);
                LDSM4(af[nxt][1], st + aOff[mi + 1][1]);
            }
#pragma unroll
            for (int ni = 0; ni < 4; ni++)
                MMA_F16(acc[mi][ni], af[cur][0], bf[0][ni]);
#pragma unroll
            for (int ni = 0; ni < 4; ni++)
                MMA_F16(acc[mi][ni], af[cur][1], bf[1][ni]);

            if (mi == 0 && doLoad) {
                CP_ASYNC16(ld + B_OFF + d0,        pyh);
            }
            if (mi == 1 && doLoad) {
                CP_ASYNC16(ld + B_OFF + d0 + 4096, pyh + ROW64);
            }
        }
        if (doLoad) { pxh += BKq; pyh += BKq; }
        CP_COMMIT();                     // exactly one group per iter
    }

    // ---- fused cosine epilogue (reciprocal multiplies, streaming stores) ----
    const int gq = lane >> 2;
    const int tq = lane & 3;

    float yi0[4], yi1[4];
#pragma unroll
    for (int ni = 0; ni < 4; ni++) {
        int n = rowB0 + wn * 32 + ni * 8 + 2 * tq;
        yi0[ni] = g_yin[b * Nq + n];
        yi1[ni] = g_yin[b * Nq + n + 1];
    }

#pragma unroll
    for (int mi = 0; mi < 4; mi++) {
        int mA = rowA0 + wm * 64 + mi * 16 + gq;
        float xiA = g_xin[b * Nq + mA];
        float xiB = g_xin[b * Nq + mA + 8];
        float* orowA = out + ((size_t)b * Nq + mA) * Nq + rowB0 + wn * 32;
        float* orowB = orowA + 8 * (size_t)Nq;
#pragma unroll
        for (int ni = 0; ni < 4; ni++) {
            STG_CS_V2(orowA + ni * 8 + 2 * tq,
                      acc[mi][ni][0] * (xiA * yi0[ni]),
                      acc[mi][ni][1] * (xiA * yi1[ni]));
            STG_CS_V2(orowB + ni * 8 + 2 * tq,
                      acc[mi][ni][2] * (xiB * yi0[ni]),
                      acc[mi][ni][3] * (xiB * yi1[ni]));
        }
    }
}

// ---------------------------------------------------------------------------
extern "C" void kernel_launch(void* const* d_in, const int* in_sizes, int n_in,
                              void* d_out, int out_size) {
    const float* x = (const float*)d_in[0];
    const float* y = (const float*)d_in[1];
    float* out = (float*)d_out;

    prep_kernel<<<(Bq * Nq + 7) / 8, 256>>>(x, y);

    cudaFuncSetAttribute(cosine_mma_kernel,
                         cudaFuncAttributeMaxDynamicSharedMemorySize, SMEM_TOTAL);
    dim3 grid(Nq / BNq, Nq / BMq, Bq);   // (16, 16, 8)
    cosine_mma_kernel<<<grid, 256, SMEM_TOTAL>>>(out);
}

// round 17
// speedup vs baseline: 1.0957x; 1.0509x over previous
#include <cuda_runtime.h>
#include <cuda_fp16.h>
#include <cstdint>

// ============================================================================
// out[b,n,m] = <x[b,n,:], y[b,m,:]> / max(||x[b,n]|| * ||y[b,m]||, eps)
//   x, y: [8, 2048, 512] fp32 ; out: [8, 2048, 2048] fp32
//
// Round 17: R14 config (122.8us best) + PRE-NORMALIZED fp16 operands:
//   prep stores fp16(x/||x||), fp16(y/||y||)  ->  acc IS the cosine.
//   Epilogue = pure streaming stores (no norm loads, no FMULs).
//   CTA 128x64, 128 thr, 4-stage single-barrier ring, 4 CTAs/SM,
//   precomputed LDSM offsets, interleaved cp.async.
// ============================================================================

#define Bq 8
#define Nq 2048
#define Dq 512

#define BMq 128
#define BNq 64
#define BKq 32                 // 32 fp16 = 64B per row
#define KITER (Dq / BKq)       // 16

// per-stage: A 8K | B 4K = 12KB; 4 stages = 48KB
#define A_OFF      0
#define B_OFF      8192
#define STG_BYTES  12288
#define SMEM_TOTAL (4 * STG_BYTES)   // 49152

#define ROW32 (32 * Dq)

__device__ __half g_xh[Bq * Nq * Dq];   // fp16(x / ||x_row||)
__device__ __half g_yh[Bq * Nq * Dq];   // fp16(y / ||y_row||)

// ---------------------------------------------------------------------------
__device__ __forceinline__ uint32_t smem_u32(const void* p) {
    uint32_t a;
    asm("{ .reg .u64 t; cvta.to.shared.u64 t, %1; cvt.u32.u64 %0, t; }"
        : "=r"(a) : "l"(p));
    return a;
}

#define CP_ASYNC16(dst, src) \
    asm volatile("cp.async.cg.shared.global [%0], [%1], 16;" \
                 :: "r"(dst), "l"(src) : "memory")
#define CP_COMMIT() asm volatile("cp.async.commit_group;" ::: "memory")
#define CP_WAIT2()  asm volatile("cp.async.wait_group 2;" ::: "memory")

#define LDSM4(r, addr) \
    asm volatile("ldmatrix.sync.aligned.m8n8.x4.shared.b16 {%0,%1,%2,%3}, [%4];" \
                 : "=r"((r)[0]), "=r"((r)[1]), "=r"((r)[2]), "=r"((r)[3]) \
                 : "r"(addr))

#define MMA_F16(d, a, bf) \
    asm volatile("mma.sync.aligned.m16n8k16.row.col.f32.f16.f16.f32 " \
                 "{%0,%1,%2,%3}, {%4,%5,%6,%7}, {%8,%9}, {%0,%1,%2,%3};" \
                 : "+f"((d)[0]), "+f"((d)[1]), "+f"((d)[2]), "+f"((d)[3]) \
                 : "r"((a)[0]), "r"((a)[1]), "r"((a)[2]), "r"((a)[3]), \
                   "r"((bf)[0]), "r"((bf)[1]))

#define STG_CS_V2(addr, vx, vy) \
    asm volatile("st.global.cs.v2.f32 [%0], {%1, %2};" \
                 :: "l"(addr), "f"(vx), "f"(vy) : "memory")

// paired-row swizzle for 64B rows
__device__ __forceinline__ uint32_t swz64(int r, int c) {
    uint32_t line = (uint32_t)r >> 1;
    uint32_t ce = (((uint32_t)r & 1u) << 2) | (uint32_t)c;
    return line * 128u + ((ce ^ (line & 7u)) << 4);
}

// ---------------------------------------------------------------------------
// Prep: one warp per row. Row (512 floats) held in registers (16/lane):
// sum-squares -> warp reduce -> scale by rsqrt -> fp16 store.
// ---------------------------------------------------------------------------
__global__ void __launch_bounds__(256) prep_kernel(const float* __restrict__ X,
                                                   const float* __restrict__ Y) {
    int row = blockIdx.x * 8 + (threadIdx.x >> 5);
    int lane = threadIdx.x & 31;
    if (row >= Bq * Nq) return;

    const float4* px = reinterpret_cast<const float4*>(X + (size_t)row * Dq);
    const float4* py = reinterpret_cast<const float4*>(Y + (size_t)row * Dq);

    float4 xa[4], ya[4];
    float sx = 0.f, sy = 0.f;
#pragma unroll
    for (int v = 0; v < 4; v++) {
        int i = v * 32 + lane;
        xa[v] = px[i];
        sx = fmaf(xa[v].x, xa[v].x, sx); sx = fmaf(xa[v].y, xa[v].y, sx);
        sx = fmaf(xa[v].z, xa[v].z, sx); sx = fmaf(xa[v].w, xa[v].w, sx);
        ya[v] = py[i];
        sy = fmaf(ya[v].x, ya[v].x, sy); sy = fmaf(ya[v].y, ya[v].y, sy);
        sy = fmaf(ya[v].z, ya[v].z, sy); sy = fmaf(ya[v].w, ya[v].w, sy);
    }
#pragma unroll
    for (int off = 16; off > 0; off >>= 1) {
        sx += __shfl_xor_sync(0xFFFFFFFFu, sx, off);
        sy += __shfl_xor_sync(0xFFFFFFFFu, sy, off);
    }
    // exact fp32 1/||.|| (norm >= ~18 for these inputs; eps path dead)
    const float rx = 1.0f / fmaxf(sqrtf(sx), 1e-30f);
    const float ry = 1.0f / fmaxf(sqrtf(sy), 1e-30f);

#pragma unroll
    for (int v = 0; v < 4; v++) {
        int i = v * 32 + lane;
        size_t off = (size_t)row * Dq + (size_t)i * 4;
        __half2 h0 = __float22half2_rn(make_float2(xa[v].x * rx, xa[v].y * rx));
        __half2 h1 = __float22half2_rn(make_float2(xa[v].z * rx, xa[v].w * rx));
        *reinterpret_cast<__half2*>(g_xh + off)     = h0;
        *reinterpret_cast<__half2*>(g_xh + off + 2) = h1;
        h0 = __float22half2_rn(make_float2(ya[v].x * ry, ya[v].y * ry));
        h1 = __float22half2_rn(make_float2(ya[v].z * ry, ya[v].w * ry));
        *reinterpret_cast<__half2*>(g_yh + off)     = h0;
        *reinterpret_cast<__half2*>(g_yh + off + 2) = h1;
    }
}

// ---------------------------------------------------------------------------
// GEMM kernel. Grid (32,16,8), 128 threads = 4 warps (2x2), warp tile 64x32.
// 4 CTAs per SM, 4-stage single-barrier pipeline, interleaved loads.
// Accumulator is the cosine directly (operands pre-normalized).
// ---------------------------------------------------------------------------
__global__ void __launch_bounds__(128, 4) cosine_mma_kernel(float* __restrict__ out) {
    extern __shared__ char smem[];
    const uint32_t sb = smem_u32(smem);

    const int tid = threadIdx.x;
    const int wid = tid >> 5, lane = tid & 31;
    const int wm = wid >> 1;          // 0..1  (64 m-rows)
    const int wn = wid & 1;           // 0..1  (32 n-cols)
    const int tileM = blockIdx.x;     // y tile (64 rows)
    const int tileN = blockIdx.y;     // x tile (128 rows)
    const int b = blockIdx.z;
    const int rowA0 = tileN * BMq;
    const int rowB0 = tileM * BNq;

    // ---- cp.async setup ----
    const int r0 = tid >> 2;          // 0..31
    const int c0 = tid & 3;
    const uint32_t d0 = swz64(r0, c0);
    const __half* pxh = g_xh + (size_t)(b * Nq + rowA0 + r0) * Dq + c0 * 8;
    const __half* pyh = g_yh + (size_t)(b * Nq + rowB0 + r0) * Dq + c0 * 8;

#define LOAD_STAGE_ALL(ST) do {                                      \
        CP_ASYNC16((ST) + A_OFF + d0,        pxh);                   \
        CP_ASYNC16((ST) + A_OFF + d0 + 2048, pxh + ROW32);           \
        CP_ASYNC16((ST) + A_OFF + d0 + 4096, pxh + 2 * ROW32);       \
        CP_ASYNC16((ST) + A_OFF + d0 + 6144, pxh + 3 * ROW32);       \
        CP_ASYNC16((ST) + B_OFF + d0,        pyh);                   \
        CP_ASYNC16((ST) + B_OFF + d0 + 2048, pyh + ROW32);           \
        pxh += BKq; pyh += BKq;                                      \
    } while (0)

    float acc[4][4][4];
#pragma unroll
    for (int i = 0; i < 4; i++)
#pragma unroll
        for (int j = 0; j < 4; j++)
#pragma unroll
            for (int r = 0; r < 4; r++) acc[i][j][r] = 0.f;

    // prologue: 3 stages in flight (k-tiles 0,1,2)
    LOAD_STAGE_ALL(sb + 0 * STG_BYTES); CP_COMMIT();
    LOAD_STAGE_ALL(sb + 1 * STG_BYTES); CP_COMMIT();
    LOAD_STAGE_ALL(sb + 2 * STG_BYTES); CP_COMMIT();

    // ---- fully precomputed fragment smem offsets ----
    const int rowSel = (lane & 7) + (((lane >> 3) & 1) << 3);  // 0..15
    const uint32_t kcq = (uint32_t)(lane >> 4);                // 0/1

    uint32_t aOff[4][2], bOff[2][2];
#pragma unroll
    for (int mi = 0; mi < 4; mi++) {
        int row = wm * 64 + mi * 16 + rowSel;
        uint32_t line = (uint32_t)(row >> 1);
        uint32_t par  = ((uint32_t)row & 1u) << 2;
#pragma unroll
        for (int k16 = 0; k16 < 2; k16++) {
            uint32_t kc = (uint32_t)(k16 * 2) + kcq;
            aOff[mi][k16] = A_OFF + line * 128u + (((par | kc) ^ (line & 7u)) << 4);
        }
    }
#pragma unroll
    for (int nj = 0; nj < 2; nj++) {
        int row = wn * 32 + nj * 16 + rowSel;
        uint32_t line = (uint32_t)(row >> 1);
        uint32_t par  = ((uint32_t)row & 1u) << 2;
#pragma unroll
        for (int k16 = 0; k16 < 2; k16++) {
            uint32_t kc = (uint32_t)(k16 * 2) + kcq;
            bOff[nj][k16] = B_OFF + line * 128u + (((par | kc) ^ (line & 7u)) << 4);
        }
    }

    for (int t = 0; t < KITER; t++) {
        CP_WAIT2();                      // stage t&3 ready
        __syncthreads();                 // everyone finished iter t-1 reads

        const uint32_t st = sb + (t & 3) * STG_BYTES;
        const bool doLoad = (t + 3 < KITER);
        const uint32_t ld = sb + ((t + 3) & 3) * STG_BYTES;  // == (t-1)&3, safe

        // ---- B fragments for BOTH k16 halves ----
        uint32_t bf[2][4][2];
#pragma unroll
        for (int k16 = 0; k16 < 2; k16++) {
#pragma unroll
            for (int nj = 0; nj < 2; nj++) {
                uint32_t tb[4];
                LDSM4(tb, st + bOff[nj][k16]);
                bf[k16][2 * nj][0] = tb[0]; bf[k16][2 * nj][1] = tb[2];
                bf[k16][2 * nj + 1][0] = tb[1]; bf[k16][2 * nj + 1][1] = tb[3];
            }
        }
        // interleaved loads, chunk 1/3 (A rows 0..63)
        if (doLoad) {
            CP_ASYNC16(ld + A_OFF + d0,        pxh);
            CP_ASYNC16(ld + A_OFF + d0 + 2048, pxh + ROW32);
        }

        // ---- A per mi (both k16), double-buffered; interleaved loads ----
        uint32_t af[2][2][4];
        LDSM4(af[0][0], st + aOff[0][0]);
        LDSM4(af[0][1], st + aOff[0][1]);
#pragma unroll
        for (int mi = 0; mi < 4; mi++) {
            const int cur = mi & 1, nxt = cur ^ 1;
            if (mi < 3) {
                LDSM4(af[nxt][0], st + aOff[mi + 1][0]);
                LDSM4(af[nxt][1], st + aOff[mi + 1][1]);
            }
#pragma unroll
            for (int ni = 0; ni < 4; ni++)
                MMA_F16(acc[mi][ni], af[cur][0], bf[0][ni]);
#pragma unroll
            for (int ni = 0; ni < 4; ni++)
                MMA_F16(acc[mi][ni], af[cur][1], bf[1][ni]);

            if (mi == 0 && doLoad) {   // chunk 2/3 (A rows 64..127)
                CP_ASYNC16(ld + A_OFF + d0 + 4096, pxh + 2 * ROW32);
                CP_ASYNC16(ld + A_OFF + d0 + 6144, pxh + 3 * ROW32);
            }
            if (mi == 1 && doLoad) {   // chunk 3/3 (B rows)
                CP_ASYNC16(ld + B_OFF + d0,        pyh);
                CP_ASYNC16(ld + B_OFF + d0 + 2048, pyh + ROW32);
            }
        }
        if (doLoad) { pxh += BKq; pyh += BKq; }
        CP_COMMIT();                     // exactly one group per iter
    }

    // ---- epilogue: acc IS the cosine; pure streaming stores ----
    const int gq = lane >> 2;
    const int tq = lane & 3;

#pragma unroll
    for (int mi = 0; mi < 4; mi++) {
        int mA = rowA0 + wm * 64 + mi * 16 + gq;
        float* orowA = out + ((size_t)b * Nq + mA) * Nq + rowB0 + wn * 32;
        float* orowB = orowA + 8 * (size_t)Nq;
#pragma unroll
        for (int ni = 0; ni < 4; ni++) {
            STG_CS_V2(orowA + ni * 8 + 2 * tq, acc[mi][ni][0], acc[mi][ni][1]);
            STG_CS_V2(orowB + ni * 8 + 2 * tq, acc[mi][ni][2], acc[mi][ni][3]);
        }
    }
}

// ---------------------------------------------------------------------------
extern "C" void kernel_launch(void* const* d_in, const int* in_sizes, int n_in,
                              void* d_out, int out_size) {
    const float* x = (const float*)d_in[0];
    const float* y = (const float*)d_in[1];
    float* out = (float*)d_out;

    prep_kernel<<<(Bq * Nq + 7) / 8, 256>>>(x, y);

    cudaFuncSetAttribute(cosine_mma_kernel,
                         cudaFuncAttributeMaxDynamicSharedMemorySize, SMEM_TOTAL);
    dim3 grid(Nq / BNq, Nq / BMq, Bq);   // (32, 16, 8)
    cosine_mma_kernel<<<grid, 128, SMEM_TOTAL>>>(out);
}